// round 6
// baseline (speedup 1.0000x reference)
#include <cuda_runtime.h>
#include <math.h>

#define SEQ 1024

// Scratch (device globals; no allocation allowed)
__device__ float g_q[SEQ*256];
__device__ float g_k[SEQ*256];
__device__ float g_v[SEQ*256];
__device__ float g_ctx[SEQ*256];
__device__ float g_rel[SEQ*SEQ];

// ---- helpers -------------------------------------------------------------
__device__ __forceinline__ unsigned tf32r(float x) {
    unsigned r;
    asm("cvt.rna.tf32.f32 %0, %1;" : "=r"(r) : "f"(x));
    return r;
}

__device__ __forceinline__ void mma_tf32(float* d, const unsigned* a, const unsigned* b) {
    asm volatile(
        "mma.sync.aligned.m16n8k8.row.col.f32.tf32.tf32.f32 "
        "{%0,%1,%2,%3}, {%4,%5,%6,%7}, {%8,%9}, {%0,%1,%2,%3};\n"
        : "+f"(d[0]), "+f"(d[1]), "+f"(d[2]), "+f"(d[3])
        : "r"(a[0]), "r"(a[1]), "r"(a[2]), "r"(a[3]),
          "r"(b[0]), "r"(b[1]));
}

__device__ __forceinline__ void cp16(void* dst, const void* src) {
    unsigned d = (unsigned)__cvta_generic_to_shared(dst);
    asm volatile("cp.async.ca.shared.global [%0], [%1], 16;\n" :: "r"(d), "l"(src));
}
#define CP_COMMIT() asm volatile("cp.async.commit_group;\n")
template <int N> __device__ __forceinline__ void cp_wait() {
    asm volatile("cp.async.wait_group %0;\n" :: "n"(N));
}

// ---- GEMM tile: C[32x64] = A[32x256] @ B[64x256]^T (+bias), 128 threads --
// BK=64 (4 chunks), 2-stage cp.async, dynamic smem 52KB.
// 4 warps, warp tile 32m x 16n (2 m-frags x 2 n-frags).
__device__ __forceinline__ void gemm_dev(const float* __restrict__ A,
                                         const float* __restrict__ B,
                                         float* __restrict__ C,
                                         const float* __restrict__ bias,
                                         bool round_out,
                                         int m0, int n0) {
    extern __shared__ __align__(16) char smg[];
    float* As = (float*)smg;                 // [2][32][68]
    float* Bs = (float*)(smg + 17408);       // [2][64][68]
    int tid = threadIdx.x;
    int warp = tid >> 5, lane = tid & 31;
    int g = lane >> 2, t = lane & 3;
    int wn = warp;

    float acc[2][2][4];
    #pragma unroll
    for (int i = 0; i < 2; i++)
        #pragma unroll
        for (int j = 0; j < 2; j++)
            #pragma unroll
            for (int r = 0; r < 4; r++) acc[i][j][r] = 0.f;

    auto stage = [&](int s, int k0) {
        float* Ad = As + s * 32 * 68;
        float* Bd = Bs + s * 64 * 68;
        #pragma unroll
        for (int i2 = 0; i2 < 4; i2++) {      // A: 32 rows x 16 f4
            int f = tid + i2 * 128;
            int r = f >> 4, c4 = f & 15;
            cp16(Ad + r * 68 + c4 * 4, A + (m0 + r) * 256 + k0 + c4 * 4);
        }
        #pragma unroll
        for (int i2 = 0; i2 < 8; i2++) {      // B: 64 rows x 16 f4
            int f = tid + i2 * 128;
            int r = f >> 4, c4 = f & 15;
            cp16(Bd + r * 68 + c4 * 4, B + (n0 + r) * 256 + k0 + c4 * 4);
        }
        CP_COMMIT();
    };

    stage(0, 0);
    for (int ch = 0; ch < 4; ch++) {
        int s = ch & 1;
        if (ch < 3) stage(s ^ 1, (ch + 1) * 64);
        if (ch < 3) cp_wait<1>(); else cp_wait<0>();
        __syncthreads();
        float* Ac = As + s * 32 * 68;
        float* Bc = Bs + s * 64 * 68;
        #pragma unroll
        for (int ks = 0; ks < 8; ks++) {
            unsigned a[2][4], b[2][2];
            #pragma unroll
            for (int am = 0; am < 2; am++) {
                int row = am * 16 + g;
                a[am][0] = tf32r(Ac[(row    ) * 68 + ks*8 + t]);
                a[am][1] = tf32r(Ac[(row + 8) * 68 + ks*8 + t]);
                a[am][2] = tf32r(Ac[(row    ) * 68 + ks*8 + t + 4]);
                a[am][3] = tf32r(Ac[(row + 8) * 68 + ks*8 + t + 4]);
            }
            #pragma unroll
            for (int bn = 0; bn < 2; bn++) {
                int nr = wn * 16 + bn * 8 + g;
                b[bn][0] = tf32r(Bc[nr * 68 + ks*8 + t]);
                b[bn][1] = tf32r(Bc[nr * 68 + ks*8 + t + 4]);
            }
            #pragma unroll
            for (int am = 0; am < 2; am++)
                #pragma unroll
                for (int bn = 0; bn < 2; bn++)
                    mma_tf32(acc[am][bn], a[am], b[bn]);
        }
        __syncthreads();
    }

    #pragma unroll
    for (int am = 0; am < 2; am++) {
        #pragma unroll
        for (int bn = 0; bn < 2; bn++) {
            int col = n0 + wn * 16 + bn * 8 + 2 * t;
            float bx = bias ? bias[col] : 0.f;
            float by = bias ? bias[col + 1] : 0.f;
            int r0 = m0 + am * 16 + g;
            float v0 = acc[am][bn][0] + bx, v1 = acc[am][bn][1] + by;
            float v2 = acc[am][bn][2] + bx, v3 = acc[am][bn][3] + by;
            if (round_out) {
                v0 = __uint_as_float(tf32r(v0)); v1 = __uint_as_float(tf32r(v1));
                v2 = __uint_as_float(tf32r(v2)); v3 = __uint_as_float(tf32r(v3));
            }
            *(float2*)(C + r0 * 256 + col)       = make_float2(v0, v1);
            *(float2*)(C + (r0 + 8) * 256 + col) = make_float2(v2, v3);
        }
    }
}

// ---- prep: z<3 = projections, z==3 = rel precompute ----------------------
__global__ void __launch_bounds__(128) prep_kernel(
    const float* __restrict__ Q, const float* __restrict__ K,
    const float* __restrict__ V, const float* __restrict__ Wq,
    const float* __restrict__ Wk, const float* __restrict__ Wv,
    const float* __restrict__ pos) {
    int z = blockIdx.z;
    if (z < 3) {
        const float *A, *B; float* C;
        if (z == 0)      { A = Q; B = Wq; C = g_q; }
        else if (z == 1) { A = K; B = Wk; C = g_k; }
        else             { A = V; B = Wv; C = g_v; }
        gemm_dev(A, B, C, nullptr, true, blockIdx.x * 32, blockIdx.y * 64);
    } else {
        // rel[i][j] = log(|p_i - p_j| + 1); 128 blocks x 8 rows each
        int bid = blockIdx.y * 32 + blockIdx.x;          // 0..127
        int tid = threadIdx.x;
        int i = bid * 8 + (tid >> 4);
        int jb = (tid & 15) * 64;
        float pi = __ldg(pos + i);
        #pragma unroll
        for (int jj = 0; jj < 16; jj++) {
            int j4 = jb + jj * 4;
            float4 pj = *(const float4*)(pos + j4);
            float4 r;
            r.x = __logf(fabsf(pi - pj.x) + 1.f);
            r.y = __logf(fabsf(pi - pj.y) + 1.f);
            r.z = __logf(fabsf(pi - pj.z) + 1.f);
            r.w = __logf(fabsf(pi - pj.w) + 1.f);
            *(float4*)(g_rel + i * 1024 + j4) = r;
        }
    }
}

__global__ void __launch_bounds__(128) out_kernel(
    const float* __restrict__ Wo, const float* __restrict__ bo,
    float* __restrict__ out) {
    gemm_dev(g_ctx, Wo, out, bo, false, blockIdx.x * 32, blockIdx.y * 64);
}

// ---- Flash attention: warpgroup-split over KV, K+V double-buffered -------
// Grid (16 q-tiles x 8 heads), block 256 = 2 warpgroups of 4 warps.
// wg0: chunks 0-7 (k 0-511), wg1: chunks 8-15; named barriers decouple wgs.
#define BARW() asm volatile("bar.sync %0, 128;" :: "r"(wg + 1))

__global__ void __launch_bounds__(256) attn_kernel(const float* __restrict__ Wr) {
    extern __shared__ __align__(16) char sm[];
    float*    Ksb   = (float*)sm;                    // [wg][2][64][36]
    float*    Vsb   = (float*)(sm + 36864);          // [wg][2][64][36]
    unsigned* Psb   = (unsigned*)(sm + 73728);       // [wg][64][68]
    float*    coeff = (float*)(sm + 108544);         // [wg][64]

    int h = blockIdx.y, q0 = blockIdx.x * 64;
    int tid = threadIdx.x, warp = tid >> 5, lane = tid & 31;
    int wg = warp >> 2, wi = warp & 3;
    int wtid = tid & 127;
    int g = lane >> 2, t = lane & 3;
    int hc = h * 32;
    const float scale = 0.0625f;

    float*    myK = Ksb + wg * 2 * 64 * 36;
    float*    myV = Vsb + wg * 2 * 64 * 36;
    unsigned* myP = Psb + wg * 64 * 68;
    unsigned* qbuf = myP;                            // q staging alias, stride 36
    float*    myC = coeff + wg * 64;

    // load q tile (tf32-pre-rounded by prep), fold in scale
    #pragma unroll
    for (int i = 0; i < 4; i++) {
        int f = wtid + i * 128;
        int r = f >> 3, c4 = f & 7;
        float4 a4 = *(const float4*)(g_q + (q0 + r) * 256 + hc + c4 * 4);
        qbuf[r*36 + c4*4+0] = __float_as_uint(a4.x * scale);
        qbuf[r*36 + c4*4+1] = __float_as_uint(a4.y * scale);
        qbuf[r*36 + c4*4+2] = __float_as_uint(a4.z * scale);
        qbuf[r*36 + c4*4+3] = __float_as_uint(a4.w * scale);
    }
    BARW();

    // coeff[r] = sum_d q_scaled[r][d] * Wr[h*32+d]  (rows owned by this warp)
    {
        int rr = wi * 16 + (lane >> 1);
        int half = lane & 1;
        float c = 0.f;
        #pragma unroll
        for (int d = 0; d < 16; d++)
            c += __uint_as_float(qbuf[rr*36 + half*16 + d]) * Wr[hc + half*16 + d];
        c += __shfl_xor_sync(0xffffffffu, c, 1);
        if (!half) myC[rr] = c;
    }
    __syncwarp();

    int r0 = wi * 16 + g, r1 = r0 + 8;
    float cf0 = myC[r0], cf1 = myC[r1];
    const float* relp0 = g_rel + (q0 + r0) * 1024;
    const float* relp1 = g_rel + (q0 + r1) * 1024;

    unsigned qa[4][4];
    #pragma unroll
    for (int ks = 0; ks < 4; ks++) {
        qa[ks][0] = qbuf[r0*36 + ks*8 + t];
        qa[ks][1] = qbuf[r1*36 + ks*8 + t];
        qa[ks][2] = qbuf[r0*36 + ks*8 + t + 4];
        qa[ks][3] = qbuf[r1*36 + ks*8 + t + 4];
    }
    BARW();   // qbuf dead; P region may now be written

    auto stageK = [&](int s, int k0) {
        float* dst = myK + s * 64 * 36;
        #pragma unroll
        for (int i = 0; i < 4; i++) {
            int f = wtid + i * 128;
            int r = f >> 3, c4 = f & 7;
            cp16(dst + r * 36 + c4 * 4, g_k + (k0 + r) * 256 + hc + c4 * 4);
        }
        CP_COMMIT();
    };
    auto stageV = [&](int s, int k0) {
        float* dst = myV + s * 64 * 36;
        #pragma unroll
        for (int i = 0; i < 4; i++) {
            int f = wtid + i * 128;
            int r = f >> 3, c4 = f & 7;
            cp16(dst + r * 36 + c4 * 4, g_v + (k0 + r) * 256 + hc + c4 * 4);
        }
        CP_COMMIT();
    };

    float m0 = -INFINITY, m1 = -INFINITY, l0 = 0.f, l1 = 0.f;
    float O[4][4];
    #pragma unroll
    for (int nf = 0; nf < 4; nf++)
        #pragma unroll
        for (int r = 0; r < 4; r++) O[nf][r] = 0.f;

    int kbase = wg * 512;
    stageK(0, kbase);
    stageV(0, kbase);

    for (int ch = 0; ch < 8; ch++) {
        int s = ch & 1;
        int k0 = kbase + ch * 64;
        cp_wait<1>();          // K(ch) done (outstanding: [K(ch), V(ch)])
        BARW();
        if (ch < 7) stageK(s ^ 1, k0 + 64);   // -> [V(ch), K(ch+1)]

        float2 rb0[8], rb1[8];
        #pragma unroll
        for (int nf = 0; nf < 8; nf++) {
            rb0[nf] = *(const float2*)(relp0 + k0 + nf*8 + 2*t);
            rb1[nf] = *(const float2*)(relp1 + k0 + nf*8 + 2*t);
        }

        float S[8][4];
        #pragma unroll
        for (int nf = 0; nf < 8; nf++)
            #pragma unroll
            for (int r = 0; r < 4; r++) S[nf][r] = 0.f;
        float* Kc = myK + s * 64 * 36;
        #pragma unroll
        for (int ks = 0; ks < 4; ks++) {
            #pragma unroll
            for (int nf = 0; nf < 8; nf++) {
                unsigned b[2];
                int nr = nf * 8 + g;
                b[0] = __float_as_uint(Kc[nr*36 + ks*8 + t]);
                b[1] = __float_as_uint(Kc[nr*36 + ks*8 + t + 4]);
                mma_tf32(S[nf], qa[ks], b);
            }
        }

        #pragma unroll
        for (int nf = 0; nf < 8; nf++) {
            S[nf][0] += cf0 * rb0[nf].x;
            S[nf][1] += cf0 * rb0[nf].y;
            S[nf][2] += cf1 * rb1[nf].x;
            S[nf][3] += cf1 * rb1[nf].y;
        }

        float mx0 = -INFINITY, mx1 = -INFINITY;
        #pragma unroll
        for (int nf = 0; nf < 8; nf++) {
            mx0 = fmaxf(mx0, fmaxf(S[nf][0], S[nf][1]));
            mx1 = fmaxf(mx1, fmaxf(S[nf][2], S[nf][3]));
        }
        mx0 = fmaxf(mx0, __shfl_xor_sync(0xffffffffu, mx0, 1));
        mx0 = fmaxf(mx0, __shfl_xor_sync(0xffffffffu, mx0, 2));
        mx1 = fmaxf(mx1, __shfl_xor_sync(0xffffffffu, mx1, 1));
        mx1 = fmaxf(mx1, __shfl_xor_sync(0xffffffffu, mx1, 2));
        float mn0 = fmaxf(m0, mx0), mn1 = fmaxf(m1, mx1);
        float corr0 = __expf(m0 - mn0), corr1 = __expf(m1 - mn1);
        m0 = mn0; m1 = mn1;

        float ps0 = 0.f, ps1 = 0.f;
        #pragma unroll
        for (int nf = 0; nf < 8; nf++) {
            float p00 = __expf(S[nf][0] - mn0);
            float p01 = __expf(S[nf][1] - mn0);
            float p10 = __expf(S[nf][2] - mn1);
            float p11 = __expf(S[nf][3] - mn1);
            ps0 += p00 + p01; ps1 += p10 + p11;
            myP[r0*68 + nf*8 + 2*t]     = tf32r(p00);
            myP[r0*68 + nf*8 + 2*t + 1] = tf32r(p01);
            myP[r1*68 + nf*8 + 2*t]     = tf32r(p10);
            myP[r1*68 + nf*8 + 2*t + 1] = tf32r(p11);
        }
        ps0 += __shfl_xor_sync(0xffffffffu, ps0, 1);
        ps0 += __shfl_xor_sync(0xffffffffu, ps0, 2);
        ps1 += __shfl_xor_sync(0xffffffffu, ps1, 1);
        ps1 += __shfl_xor_sync(0xffffffffu, ps1, 2);
        l0 = l0 * corr0 + ps0;
        l1 = l1 * corr1 + ps1;
        #pragma unroll
        for (int nf = 0; nf < 4; nf++) {
            O[nf][0] *= corr0; O[nf][1] *= corr0;
            O[nf][2] *= corr1; O[nf][3] *= corr1;
        }
        __syncwarp();   // order myP STS before LDS (rows warp-private)

        if (ch < 7) cp_wait<1>(); else cp_wait<0>();   // V(ch) done
        BARW();

        float* Vc = myV + s * 64 * 36;
        #pragma unroll
        for (int ks = 0; ks < 8; ks++) {
            unsigned pa[4];
            pa[0] = myP[r0*68 + ks*8 + t];
            pa[1] = myP[r1*68 + ks*8 + t];
            pa[2] = myP[r0*68 + ks*8 + t + 4];
            pa[3] = myP[r1*68 + ks*8 + t + 4];
            #pragma unroll
            for (int nf = 0; nf < 4; nf++) {
                unsigned b[2];
                b[0] = __float_as_uint(Vc[(ks*8 + t    )*36 + nf*8 + g]);
                b[1] = __float_as_uint(Vc[(ks*8 + t + 4)*36 + nf*8 + g]);
                mma_tf32(O[nf], pa, b);
            }
        }
        if (ch < 7) stageV(s ^ 1, k0 + 64);   // other buffer: no barrier needed
    }

    // ---- merge the two warpgroup partials ----
    __syncthreads();                 // both wgs finished; Ks region reusable
    float* Om = (float*)sm;          // [128][20]
    if (wg == 1) {
        float* o = Om + wtid * 20;
        #pragma unroll
        for (int nf = 0; nf < 4; nf++)
            #pragma unroll
            for (int j = 0; j < 4; j++) o[nf*4 + j] = O[nf][j];
        o[16] = m0; o[17] = l0; o[18] = m1; o[19] = l1;
    }
    __syncthreads();
    if (wg == 0) {
        float* o = Om + wtid * 20;
        float mB0 = o[16], lB0 = o[17], mB1 = o[18], lB1 = o[19];
        float M0 = fmaxf(m0, mB0), M1 = fmaxf(m1, mB1);
        float eA0 = __expf(m0 - M0), eB0 = __expf(mB0 - M0);
        float eA1 = __expf(m1 - M1), eB1 = __expf(mB1 - M1);
        float inv0 = 1.f / (l0 * eA0 + lB0 * eB0);
        float inv1 = 1.f / (l1 * eA1 + lB1 * eB1);
        #pragma unroll
        for (int nf = 0; nf < 4; nf++) {
            int col = hc + nf * 8 + 2 * t;
            float v0 = (O[nf][0] * eA0 + o[nf*4+0] * eB0) * inv0;
            float v1 = (O[nf][1] * eA0 + o[nf*4+1] * eB0) * inv0;
            float v2 = (O[nf][2] * eA1 + o[nf*4+2] * eB1) * inv1;
            float v3 = (O[nf][3] * eA1 + o[nf*4+3] * eB1) * inv1;
            *(float2*)(g_ctx + (q0 + r0) * 256 + col) = make_float2(v0, v1);
            *(float2*)(g_ctx + (q0 + r1) * 256 + col) = make_float2(v2, v3);
        }
    }
}

// ---- launch --------------------------------------------------------------
extern "C" void kernel_launch(void* const* d_in, const int* in_sizes, int n_in,
                              void* d_out, int out_size) {
    const float* V   = (const float*)d_in[0];
    const float* K   = (const float*)d_in[1];
    const float* Q   = (const float*)d_in[2];
    const float* pos = (const float*)d_in[3];
    const float* Wq  = (const float*)d_in[4];
    const float* Wk  = (const float*)d_in[5];
    const float* Wv  = (const float*)d_in[6];
    const float* Wr  = (const float*)d_in[7];
    const float* Wo  = (const float*)d_in[8];
    const float* bo  = (const float*)d_in[9];
    float* out = (float*)d_out;

    static bool attr_done = false;
    if (!attr_done) {
        cudaFuncSetAttribute(attn_kernel,
                             cudaFuncAttributeMaxDynamicSharedMemorySize, 109056);
        cudaFuncSetAttribute(prep_kernel,
                             cudaFuncAttributeMaxDynamicSharedMemorySize, 52224);
        cudaFuncSetAttribute(out_kernel,
                             cudaFuncAttributeMaxDynamicSharedMemorySize, 52224);
        attr_done = true;
    }

    prep_kernel<<<dim3(32, 4, 4), 128, 52224>>>(Q, K, V, Wq, Wk, Wv, pos);
    attn_kernel<<<dim3(16, 8), 256, 109056>>>(Wr);
    out_kernel<<<dim3(32, 4), 128, 52224>>>(Wo, bo, out);
}

// round 11
// speedup vs baseline: 1.1483x; 1.1483x over previous
#include <cuda_runtime.h>
#include <math.h>

#define SEQ 1024

// Scratch (device globals; no allocation allowed)
__device__ float g_q[SEQ*256];
__device__ float g_k[SEQ*256];
__device__ float g_v[SEQ*256];
__device__ float g_ctx[SEQ*256];
__device__ float g_rel[SEQ*SEQ];

// ---- helpers -------------------------------------------------------------
__device__ __forceinline__ unsigned tf32r(float x) {
    unsigned r;
    asm("cvt.rna.tf32.f32 %0, %1;" : "=r"(r) : "f"(x));
    return r;
}

__device__ __forceinline__ void mma_tf32(float* d, const unsigned* a, const unsigned* b) {
    asm volatile(
        "mma.sync.aligned.m16n8k8.row.col.f32.tf32.tf32.f32 "
        "{%0,%1,%2,%3}, {%4,%5,%6,%7}, {%8,%9}, {%0,%1,%2,%3};\n"
        : "+f"(d[0]), "+f"(d[1]), "+f"(d[2]), "+f"(d[3])
        : "r"(a[0]), "r"(a[1]), "r"(a[2]), "r"(a[3]),
          "r"(b[0]), "r"(b[1]));
}

__device__ __forceinline__ void cp16(void* dst, const void* src) {
    unsigned d = (unsigned)__cvta_generic_to_shared(dst);
    asm volatile("cp.async.ca.shared.global [%0], [%1], 16;\n" :: "r"(d), "l"(src));
}
#define CP_COMMIT() asm volatile("cp.async.commit_group;\n")
template <int N> __device__ __forceinline__ void cp_wait() {
    asm volatile("cp.async.wait_group %0;\n" :: "n"(N));
}

// FMA-pipe natural log for x >= 1 (no MUFU). sqrt2-centered mantissa,
// degree-12 Taylor on ln(1+t), |t| <= 0.4142 -> abs err ~8e-7.
__device__ __forceinline__ float fast_log(float x) {
    unsigned bits = __float_as_uint(x);
    int e = (int)(bits >> 23) - 127;
    float m = __uint_as_float((bits & 0x007FFFFFu) | 0x3F800000u);  // [1,2)
    if (m > 1.41421356f) { m *= 0.5f; e += 1; }
    float t = m - 1.0f;                       // [-0.2929, 0.4142]
    float p = -1.0f / 12.0f;
    p = fmaf(p, t,  1.0f / 11.0f);
    p = fmaf(p, t, -1.0f / 10.0f);
    p = fmaf(p, t,  1.0f / 9.0f);
    p = fmaf(p, t, -1.0f / 8.0f);
    p = fmaf(p, t,  1.0f / 7.0f);
    p = fmaf(p, t, -1.0f / 6.0f);
    p = fmaf(p, t,  1.0f / 5.0f);
    p = fmaf(p, t, -0.25f);
    p = fmaf(p, t,  1.0f / 3.0f);
    p = fmaf(p, t, -0.5f);
    p = fmaf(p, t,  1.0f);
    return fmaf((float)e, 0.69314718056f, p * t);
}

// ---- GEMM tile: C[32x64] = A[32x256] @ B[64x256]^T (+bias), 128 threads --
// BK=32, 2-stage cp.async. 4 warps, warp tile 32m x 16n (2 m-frags x 2 n-frags).
__device__ __forceinline__ void gemm_dev(const float* __restrict__ A,
                                         const float* __restrict__ B,
                                         float* __restrict__ C,
                                         const float* __restrict__ bias,
                                         bool round_out,
                                         int m0, int n0) {
    __shared__ __align__(16) float As[2][32][36];
    __shared__ __align__(16) float Bs[2][64][36];
    int tid = threadIdx.x;
    int warp = tid >> 5, lane = tid & 31;
    int g = lane >> 2, t = lane & 3;
    int wn = warp;

    float acc[2][2][4];
    #pragma unroll
    for (int i = 0; i < 2; i++)
        #pragma unroll
        for (int j = 0; j < 2; j++)
            #pragma unroll
            for (int r = 0; r < 4; r++) acc[i][j][r] = 0.f;

    auto stage = [&](int s, int k0) {
        #pragma unroll
        for (int i2 = 0; i2 < 2; i2++) {       // A: 32 rows x 8 f4 = 256
            int f = tid + i2 * 128;
            int r = f >> 3, c4 = f & 7;
            cp16(&As[s][r][c4 * 4], A + (m0 + r) * 256 + k0 + c4 * 4);
        }
        #pragma unroll
        for (int i2 = 0; i2 < 4; i2++) {       // B: 64 rows x 8 f4 = 512
            int f = tid + i2 * 128;
            int r = f >> 3, c4 = f & 7;
            cp16(&Bs[s][r][c4 * 4], B + (n0 + r) * 256 + k0 + c4 * 4);
        }
        CP_COMMIT();
    };

    stage(0, 0);
    for (int ch = 0; ch < 8; ch++) {
        int s = ch & 1;
        if (ch < 7) stage(s ^ 1, (ch + 1) * 32);
        if (ch < 7) cp_wait<1>(); else cp_wait<0>();
        __syncthreads();
        #pragma unroll
        for (int ks = 0; ks < 4; ks++) {
            unsigned a[2][4], b[2][2];
            #pragma unroll
            for (int am = 0; am < 2; am++) {
                int row = am * 16 + g;
                a[am][0] = tf32r(As[s][row    ][ks*8 + t]);
                a[am][1] = tf32r(As[s][row + 8][ks*8 + t]);
                a[am][2] = tf32r(As[s][row    ][ks*8 + t + 4]);
                a[am][3] = tf32r(As[s][row + 8][ks*8 + t + 4]);
            }
            #pragma unroll
            for (int bn = 0; bn < 2; bn++) {
                int nr = wn * 16 + bn * 8 + g;
                b[bn][0] = tf32r(Bs[s][nr][ks*8 + t]);
                b[bn][1] = tf32r(Bs[s][nr][ks*8 + t + 4]);
            }
            #pragma unroll
            for (int am = 0; am < 2; am++)
                #pragma unroll
                for (int bn = 0; bn < 2; bn++)
                    mma_tf32(acc[am][bn], a[am], b[bn]);
        }
        __syncthreads();
    }

    #pragma unroll
    for (int am = 0; am < 2; am++) {
        #pragma unroll
        for (int bn = 0; bn < 2; bn++) {
            int col = n0 + wn * 16 + bn * 8 + 2 * t;
            float bx = bias ? bias[col] : 0.f;
            float by = bias ? bias[col + 1] : 0.f;
            int r0 = m0 + am * 16 + g;
            float v0 = acc[am][bn][0] + bx, v1 = acc[am][bn][1] + by;
            float v2 = acc[am][bn][2] + bx, v3 = acc[am][bn][3] + by;
            if (round_out) {
                v0 = __uint_as_float(tf32r(v0)); v1 = __uint_as_float(tf32r(v1));
                v2 = __uint_as_float(tf32r(v2)); v3 = __uint_as_float(tf32r(v3));
            }
            *(float2*)(C + r0 * 256 + col)       = make_float2(v0, v1);
            *(float2*)(C + (r0 + 8) * 256 + col) = make_float2(v2, v3);
        }
    }
}

// ---- prep: z<3 = projections, z==3 = rel precompute ----------------------
__global__ void __launch_bounds__(128) prep_kernel(
    const float* __restrict__ Q, const float* __restrict__ K,
    const float* __restrict__ V, const float* __restrict__ Wq,
    const float* __restrict__ Wk, const float* __restrict__ Wv,
    const float* __restrict__ pos) {
    int z = blockIdx.z;
    if (z < 3) {
        const float *A, *B; float* C;
        if (z == 0)      { A = Q; B = Wq; C = g_q; }
        else if (z == 1) { A = K; B = Wk; C = g_k; }
        else             { A = V; B = Wv; C = g_v; }
        gemm_dev(A, B, C, nullptr, true, blockIdx.x * 32, blockIdx.y * 64);
    } else {
        // rel[i][j] = log(|p_i - p_j| + 1); 128 blocks x 8 rows, FMA-pipe log
        int bid = blockIdx.y * 32 + blockIdx.x;          // 0..127
        int tid = threadIdx.x;
        int i = bid * 8 + (tid >> 4);
        int jb = (tid & 15) * 64;
        float pi = __ldg(pos + i);
        #pragma unroll
        for (int jj = 0; jj < 16; jj++) {
            int j4 = jb + jj * 4;
            float4 pj = *(const float4*)(pos + j4);
            float4 r;
            r.x = fast_log(fabsf(pi - pj.x) + 1.f);
            r.y = fast_log(fabsf(pi - pj.y) + 1.f);
            r.z = fast_log(fabsf(pi - pj.z) + 1.f);
            r.w = fast_log(fabsf(pi - pj.w) + 1.f);
            *(float4*)(g_rel + i * 1024 + j4) = r;
        }
    }
}

__global__ void __launch_bounds__(128) out_kernel(
    const float* __restrict__ Wo, const float* __restrict__ bo,
    float* __restrict__ out) {
    gemm_dev(g_ctx, Wo, out, bo, false, blockIdx.x * 32, blockIdx.y * 64);
}

// ---- Flash attention: warpgroup-split over KV ----------------------------
// Grid (16 q-tiles x 8 heads), block 256 = 2 warpgroups of 4 warps.
// wg0: chunks 0-7 (k 0-511), wg1: chunks 8-15 (k 512-1023); private smem +
// named barriers keep them fully decoupled; (m,l,O) merged at the end.
#define BARW() asm volatile("bar.sync %0, 128;" :: "r"(wg + 1))

__global__ void __launch_bounds__(256) attn_kernel(const float* __restrict__ Wr) {
    extern __shared__ __align__(16) char sm[];
    float*    Ksb   = (float*)sm;                    // [wg][2][64][36]
    float*    Vsb   = (float*)(sm + 36864);          // [wg][64][36]
    unsigned* Psb   = (unsigned*)(sm + 55296);       // [wg][64][68]
    float*    coeff = (float*)(sm + 90112);          // [wg][64]

    int h = blockIdx.y, q0 = blockIdx.x * 64;
    int tid = threadIdx.x, warp = tid >> 5, lane = tid & 31;
    int wg = warp >> 2, wi = warp & 3;
    int wtid = tid & 127;
    int g = lane >> 2, t = lane & 3;
    int hc = h * 32;
    const float scale = 0.0625f;

    float*    myK = Ksb + wg * 2 * 64 * 36;
    float*    myV = Vsb + wg * 64 * 36;
    unsigned* myP = Psb + wg * 64 * 68;
    unsigned* qbuf = myP;                            // q staging alias, stride 36
    float*    myC = coeff + wg * 64;

    // load q tile (tf32-pre-rounded by prep), fold in scale
    #pragma unroll
    for (int i = 0; i < 4; i++) {
        int f = wtid + i * 128;
        int r = f >> 3, c4 = f & 7;
        float4 a4 = *(const float4*)(g_q + (q0 + r) * 256 + hc + c4 * 4);
        qbuf[r*36 + c4*4+0] = __float_as_uint(a4.x * scale);
        qbuf[r*36 + c4*4+1] = __float_as_uint(a4.y * scale);
        qbuf[r*36 + c4*4+2] = __float_as_uint(a4.z * scale);
        qbuf[r*36 + c4*4+3] = __float_as_uint(a4.w * scale);
    }
    BARW();

    // coeff[r] = sum_d q_scaled[r][d] * Wr[h*32+d]  (rows owned by this warp)
    {
        int rr = wi * 16 + (lane >> 1);
        int half = lane & 1;
        float c = 0.f;
        #pragma unroll
        for (int d = 0; d < 16; d++)
            c += __uint_as_float(qbuf[rr*36 + half*16 + d]) * Wr[hc + half*16 + d];
        c += __shfl_xor_sync(0xffffffffu, c, 1);
        if (!half) myC[rr] = c;
    }
    __syncwarp();

    int r0 = wi * 16 + g, r1 = r0 + 8;
    float cf0 = myC[r0], cf1 = myC[r1];
    const float* relp0 = g_rel + (q0 + r0) * 1024;
    const float* relp1 = g_rel + (q0 + r1) * 1024;

    unsigned qa[4][4];
    #pragma unroll
    for (int ks = 0; ks < 4; ks++) {
        qa[ks][0] = qbuf[r0*36 + ks*8 + t];
        qa[ks][1] = qbuf[r1*36 + ks*8 + t];
        qa[ks][2] = qbuf[r0*36 + ks*8 + t + 4];
        qa[ks][3] = qbuf[r1*36 + ks*8 + t + 4];
    }
    BARW();   // qbuf dead; P region may now be written

    auto stageK = [&](int s, int k0) {
        float* dst = myK + s * 64 * 36;
        #pragma unroll
        for (int i = 0; i < 4; i++) {
            int f = wtid + i * 128;
            int r = f >> 3, c4 = f & 7;
            cp16(dst + r * 36 + c4 * 4, g_k + (k0 + r) * 256 + hc + c4 * 4);
        }
        CP_COMMIT();
    };
    auto stageV = [&](int k0) {
        #pragma unroll
        for (int i = 0; i < 4; i++) {
            int f = wtid + i * 128;
            int r = f >> 3, c4 = f & 7;
            cp16(myV + r * 36 + c4 * 4, g_v + (k0 + r) * 256 + hc + c4 * 4);
        }
        CP_COMMIT();
    };

    float m0 = -INFINITY, m1 = -INFINITY, l0 = 0.f, l1 = 0.f;
    float O[4][4];
    #pragma unroll
    for (int nf = 0; nf < 4; nf++)
        #pragma unroll
        for (int r = 0; r < 4; r++) O[nf][r] = 0.f;

    int kbase = wg * 512;
    stageK(0, kbase);
    stageV(kbase);

    for (int ch = 0; ch < 8; ch++) {
        int s = ch & 1;
        int k0 = kbase + ch * 64;
        cp_wait<1>();          // K(ch) done (outstanding: [K(ch), V(ch)])
        BARW();
        if (ch < 7) stageK(s ^ 1, k0 + 64);

        float2 rb0[8], rb1[8];
        #pragma unroll
        for (int nf = 0; nf < 8; nf++) {
            rb0[nf] = *(const float2*)(relp0 + k0 + nf*8 + 2*t);
            rb1[nf] = *(const float2*)(relp1 + k0 + nf*8 + 2*t);
        }

        float S[8][4];
        #pragma unroll
        for (int nf = 0; nf < 8; nf++)
            #pragma unroll
            for (int r = 0; r < 4; r++) S[nf][r] = 0.f;
        float* Kc = myK + s * 64 * 36;
        #pragma unroll
        for (int ks = 0; ks < 4; ks++) {
            #pragma unroll
            for (int nf = 0; nf < 8; nf++) {
                unsigned b[2];
                int nr = nf * 8 + g;
                b[0] = __float_as_uint(Kc[nr*36 + ks*8 + t]);
                b[1] = __float_as_uint(Kc[nr*36 + ks*8 + t + 4]);
                mma_tf32(S[nf], qa[ks], b);
            }
        }

        #pragma unroll
        for (int nf = 0; nf < 8; nf++) {
            S[nf][0] += cf0 * rb0[nf].x;
            S[nf][1] += cf0 * rb0[nf].y;
            S[nf][2] += cf1 * rb1[nf].x;
            S[nf][3] += cf1 * rb1[nf].y;
        }

        float mx0 = -INFINITY, mx1 = -INFINITY;
        #pragma unroll
        for (int nf = 0; nf < 8; nf++) {
            mx0 = fmaxf(mx0, fmaxf(S[nf][0], S[nf][1]));
            mx1 = fmaxf(mx1, fmaxf(S[nf][2], S[nf][3]));
        }
        mx0 = fmaxf(mx0, __shfl_xor_sync(0xffffffffu, mx0, 1));
        mx0 = fmaxf(mx0, __shfl_xor_sync(0xffffffffu, mx0, 2));
        mx1 = fmaxf(mx1, __shfl_xor_sync(0xffffffffu, mx1, 1));
        mx1 = fmaxf(mx1, __shfl_xor_sync(0xffffffffu, mx1, 2));
        float mn0 = fmaxf(m0, mx0), mn1 = fmaxf(m1, mx1);
        float corr0 = __expf(m0 - mn0), corr1 = __expf(m1 - mn1);
        m0 = mn0; m1 = mn1;

        float ps0 = 0.f, ps1 = 0.f;
        #pragma unroll
        for (int nf = 0; nf < 8; nf++) {
            float p00 = __expf(S[nf][0] - mn0);
            float p01 = __expf(S[nf][1] - mn0);
            float p10 = __expf(S[nf][2] - mn1);
            float p11 = __expf(S[nf][3] - mn1);
            ps0 += p00 + p01; ps1 += p10 + p11;
            myP[r0*68 + nf*8 + 2*t]     = tf32r(p00);
            myP[r0*68 + nf*8 + 2*t + 1] = tf32r(p01);
            myP[r1*68 + nf*8 + 2*t]     = tf32r(p10);
            myP[r1*68 + nf*8 + 2*t + 1] = tf32r(p11);
        }
        ps0 += __shfl_xor_sync(0xffffffffu, ps0, 1);
        ps0 += __shfl_xor_sync(0xffffffffu, ps0, 2);
        ps1 += __shfl_xor_sync(0xffffffffu, ps1, 1);
        ps1 += __shfl_xor_sync(0xffffffffu, ps1, 2);
        l0 = l0 * corr0 + ps0;
        l1 = l1 * corr1 + ps1;
        #pragma unroll
        for (int nf = 0; nf < 4; nf++) {
            O[nf][0] *= corr0; O[nf][1] *= corr0;
            O[nf][2] *= corr1; O[nf][3] *= corr1;
        }
        __syncwarp();   // order myP STS before LDS (rows warp-private)

        if (ch < 7) cp_wait<1>(); else cp_wait<0>();   // V(ch) done
        BARW();

        #pragma unroll
        for (int ks = 0; ks < 8; ks++) {
            unsigned pa[4];
            pa[0] = myP[r0*68 + ks*8 + t];
            pa[1] = myP[r1*68 + ks*8 + t];
            pa[2] = myP[r0*68 + ks*8 + t + 4];
            pa[3] = myP[r1*68 + ks*8 + t + 4];
            #pragma unroll
            for (int nf = 0; nf < 4; nf++) {
                unsigned b[2];
                b[0] = __float_as_uint(myV[(ks*8 + t    )*36 + nf*8 + g]);
                b[1] = __float_as_uint(myV[(ks*8 + t + 4)*36 + nf*8 + g]);
                mma_tf32(O[nf], pa, b);
            }
        }
        BARW();                      // all wg threads done reading myV
        if (ch < 7) stageV(k0 + 64);
    }

    // ---- merge the two warpgroup partials ----
    __syncthreads();                 // both wgs finished; Ks region reusable
    float* Om = (float*)sm;          // [128][20]
    if (wg == 1) {
        float* o = Om + wtid * 20;
        #pragma unroll
        for (int nf = 0; nf < 4; nf++)
            #pragma unroll
            for (int j = 0; j < 4; j++) o[nf*4 + j] = O[nf][j];
        o[16] = m0; o[17] = l0; o[18] = m1; o[19] = l1;
    }
    __syncthreads();
    if (wg == 0) {
        float* o = Om + wtid * 20;
        float mB0 = o[16], lB0 = o[17], mB1 = o[18], lB1 = o[19];
        float M0 = fmaxf(m0, mB0), M1 = fmaxf(m1, mB1);
        float eA0 = __expf(m0 - M0), eB0 = __expf(mB0 - M0);
        float eA1 = __expf(m1 - M1), eB1 = __expf(mB1 - M1);
        float inv0 = 1.f / (l0 * eA0 + lB0 * eB0);
        float inv1 = 1.f / (l1 * eA1 + lB1 * eB1);
        #pragma unroll
        for (int nf = 0; nf < 4; nf++) {
            int col = hc + nf * 8 + 2 * t;
            float v0 = (O[nf][0] * eA0 + o[nf*4+0] * eB0) * inv0;
            float v1 = (O[nf][1] * eA0 + o[nf*4+1] * eB0) * inv0;
            float v2 = (O[nf][2] * eA1 + o[nf*4+2] * eB1) * inv1;
            float v3 = (O[nf][3] * eA1 + o[nf*4+3] * eB1) * inv1;
            *(float2*)(g_ctx + (q0 + r0) * 256 + col) = make_float2(v0, v1);
            *(float2*)(g_ctx + (q0 + r1) * 256 + col) = make_float2(v2, v3);
        }
    }
}

// ---- launch --------------------------------------------------------------
extern "C" void kernel_launch(void* const* d_in, const int* in_sizes, int n_in,
                              void* d_out, int out_size) {
    const float* V   = (const float*)d_in[0];
    const float* K   = (const float*)d_in[1];
    const float* Q   = (const float*)d_in[2];
    const float* pos = (const float*)d_in[3];
    const float* Wq  = (const float*)d_in[4];
    const float* Wk  = (const float*)d_in[5];
    const float* Wv  = (const float*)d_in[6];
    const float* Wr  = (const float*)d_in[7];
    const float* Wo  = (const float*)d_in[8];
    const float* bo  = (const float*)d_in[9];
    float* out = (float*)d_out;

    cudaFuncSetAttribute(attn_kernel,
                         cudaFuncAttributeMaxDynamicSharedMemorySize, 90624);

    prep_kernel<<<dim3(32, 4, 4), 128>>>(Q, K, V, Wq, Wk, Wv, pos);
    attn_kernel<<<dim3(16, 8), 256, 90624>>>(Wr);
    out_kernel<<<dim3(32, 4), 128>>>(Wo, bo, out);
}

// round 12
// speedup vs baseline: 1.2731x; 1.1087x over previous
#include <cuda_runtime.h>
#include <math.h>

#define SEQ 1024

// Scratch (device globals; no allocation allowed)
__device__ float g_q[SEQ*256];
__device__ float g_k[SEQ*256];
__device__ float g_v[SEQ*256];
__device__ float g_ctx[SEQ*256];
__device__ float g_rel[SEQ*SEQ];

// ---- helpers -------------------------------------------------------------
__device__ __forceinline__ unsigned tf32r(float x) {
    unsigned r;
    asm("cvt.rna.tf32.f32 %0, %1;" : "=r"(r) : "f"(x));
    return r;
}

__device__ __forceinline__ void mma_tf32(float* d, const unsigned* a, const unsigned* b) {
    asm volatile(
        "mma.sync.aligned.m16n8k8.row.col.f32.tf32.tf32.f32 "
        "{%0,%1,%2,%3}, {%4,%5,%6,%7}, {%8,%9}, {%0,%1,%2,%3};\n"
        : "+f"(d[0]), "+f"(d[1]), "+f"(d[2]), "+f"(d[3])
        : "r"(a[0]), "r"(a[1]), "r"(a[2]), "r"(a[3]),
          "r"(b[0]), "r"(b[1]));
}

__device__ __forceinline__ void cp16(void* dst, const void* src) {
    unsigned d = (unsigned)__cvta_generic_to_shared(dst);
    asm volatile("cp.async.ca.shared.global [%0], [%1], 16;\n" :: "r"(d), "l"(src));
}
#define CP_COMMIT() asm volatile("cp.async.commit_group;\n")
template <int N> __device__ __forceinline__ void cp_wait() {
    asm volatile("cp.async.wait_group %0;\n" :: "n"(N));
}

// FMA-pipe natural log for x >= 1 (no MUFU). sqrt2-centered mantissa,
// degree-12 Taylor on ln(1+t), |t| <= 0.4142 -> abs err ~8e-7.
__device__ __forceinline__ float fast_log(float x) {
    unsigned bits = __float_as_uint(x);
    int e = (int)(bits >> 23) - 127;
    float m = __uint_as_float((bits & 0x007FFFFFu) | 0x3F800000u);  // [1,2)
    if (m > 1.41421356f) { m *= 0.5f; e += 1; }
    float t = m - 1.0f;                       // [-0.2929, 0.4142]
    float p = -1.0f / 12.0f;
    p = fmaf(p, t,  1.0f / 11.0f);
    p = fmaf(p, t, -1.0f / 10.0f);
    p = fmaf(p, t,  1.0f / 9.0f);
    p = fmaf(p, t, -1.0f / 8.0f);
    p = fmaf(p, t,  1.0f / 7.0f);
    p = fmaf(p, t, -1.0f / 6.0f);
    p = fmaf(p, t,  1.0f / 5.0f);
    p = fmaf(p, t, -0.25f);
    p = fmaf(p, t,  1.0f / 3.0f);
    p = fmaf(p, t, -0.5f);
    p = fmaf(p, t,  1.0f);
    return fmaf((float)e, 0.69314718056f, p * t);
}

// ---- GEMM tile: C[32x64] = A[32x256] @ B[64x256]^T (+bias), 128 threads --
// BK=32, 2-stage cp.async. 4 warps, warp tile 32m x 16n (2 m-frags x 2 n-frags).
__device__ __forceinline__ void gemm_dev(const float* __restrict__ A,
                                         const float* __restrict__ B,
                                         float* __restrict__ C,
                                         const float* __restrict__ bias,
                                         bool round_out,
                                         int m0, int n0) {
    __shared__ __align__(16) float As[2][32][36];
    __shared__ __align__(16) float Bs[2][64][36];
    int tid = threadIdx.x;
    int warp = tid >> 5, lane = tid & 31;
    int g = lane >> 2, t = lane & 3;
    int wn = warp;

    float acc[2][2][4];
    #pragma unroll
    for (int i = 0; i < 2; i++)
        #pragma unroll
        for (int j = 0; j < 2; j++)
            #pragma unroll
            for (int r = 0; r < 4; r++) acc[i][j][r] = 0.f;

    auto stage = [&](int s, int k0) {
        #pragma unroll
        for (int i2 = 0; i2 < 2; i2++) {       // A: 32 rows x 8 f4 = 256
            int f = tid + i2 * 128;
            int r = f >> 3, c4 = f & 7;
            cp16(&As[s][r][c4 * 4], A + (m0 + r) * 256 + k0 + c4 * 4);
        }
        #pragma unroll
        for (int i2 = 0; i2 < 4; i2++) {       // B: 64 rows x 8 f4 = 512
            int f = tid + i2 * 128;
            int r = f >> 3, c4 = f & 7;
            cp16(&Bs[s][r][c4 * 4], B + (n0 + r) * 256 + k0 + c4 * 4);
        }
        CP_COMMIT();
    };

    stage(0, 0);
    for (int ch = 0; ch < 8; ch++) {
        int s = ch & 1;
        if (ch < 7) stage(s ^ 1, (ch + 1) * 32);
        if (ch < 7) cp_wait<1>(); else cp_wait<0>();
        __syncthreads();
        #pragma unroll
        for (int ks = 0; ks < 4; ks++) {
            unsigned a[2][4], b[2][2];
            #pragma unroll
            for (int am = 0; am < 2; am++) {
                int row = am * 16 + g;
                a[am][0] = tf32r(As[s][row    ][ks*8 + t]);
                a[am][1] = tf32r(As[s][row + 8][ks*8 + t]);
                a[am][2] = tf32r(As[s][row    ][ks*8 + t + 4]);
                a[am][3] = tf32r(As[s][row + 8][ks*8 + t + 4]);
            }
            #pragma unroll
            for (int bn = 0; bn < 2; bn++) {
                int nr = wn * 16 + bn * 8 + g;
                b[bn][0] = tf32r(Bs[s][nr][ks*8 + t]);
                b[bn][1] = tf32r(Bs[s][nr][ks*8 + t + 4]);
            }
            #pragma unroll
            for (int am = 0; am < 2; am++)
                #pragma unroll
                for (int bn = 0; bn < 2; bn++)
                    mma_tf32(acc[am][bn], a[am], b[bn]);
        }
        __syncthreads();
    }

    #pragma unroll
    for (int am = 0; am < 2; am++) {
        #pragma unroll
        for (int bn = 0; bn < 2; bn++) {
            int col = n0 + wn * 16 + bn * 8 + 2 * t;
            float bx = bias ? bias[col] : 0.f;
            float by = bias ? bias[col + 1] : 0.f;
            int r0 = m0 + am * 16 + g;
            float v0 = acc[am][bn][0] + bx, v1 = acc[am][bn][1] + by;
            float v2 = acc[am][bn][2] + bx, v3 = acc[am][bn][3] + by;
            if (round_out) {
                v0 = __uint_as_float(tf32r(v0)); v1 = __uint_as_float(tf32r(v1));
                v2 = __uint_as_float(tf32r(v2)); v3 = __uint_as_float(tf32r(v3));
            }
            *(float2*)(C + r0 * 256 + col)       = make_float2(v0, v1);
            *(float2*)(C + (r0 + 8) * 256 + col) = make_float2(v2, v3);
        }
    }
}

// ---- prep: z<3 = projections, z==3 = rel precompute ----------------------
__global__ void __launch_bounds__(128) prep_kernel(
    const float* __restrict__ Q, const float* __restrict__ K,
    const float* __restrict__ V, const float* __restrict__ Wq,
    const float* __restrict__ Wk, const float* __restrict__ Wv,
    const float* __restrict__ pos) {
    int z = blockIdx.z;
    if (z < 3) {
        const float *A, *B; float* C;
        if (z == 0)      { A = Q; B = Wq; C = g_q; }
        else if (z == 1) { A = K; B = Wk; C = g_k; }
        else             { A = V; B = Wv; C = g_v; }
        gemm_dev(A, B, C, nullptr, true, blockIdx.x * 32, blockIdx.y * 64);
    } else {
        // rel[i][j] = log(|p_i - p_j| + 1); 128 blocks x 8 rows, FMA-pipe log
        int bid = blockIdx.y * 32 + blockIdx.x;          // 0..127
        int tid = threadIdx.x;
        int i = bid * 8 + (tid >> 4);
        int jb = (tid & 15) * 64;
        float pi = __ldg(pos + i);
        #pragma unroll
        for (int jj = 0; jj < 16; jj++) {
            int j4 = jb + jj * 4;
            float4 pj = *(const float4*)(pos + j4);
            float4 r;
            r.x = fast_log(fabsf(pi - pj.x) + 1.f);
            r.y = fast_log(fabsf(pi - pj.y) + 1.f);
            r.z = fast_log(fabsf(pi - pj.z) + 1.f);
            r.w = fast_log(fabsf(pi - pj.w) + 1.f);
            *(float4*)(g_rel + i * 1024 + j4) = r;
        }
    }
}

__global__ void __launch_bounds__(128) out_kernel(
    const float* __restrict__ Wo, const float* __restrict__ bo,
    float* __restrict__ out) {
    gemm_dev(g_ctx, Wo, out, bo, false, blockIdx.x * 32, blockIdx.y * 64);
}

// ---- Flash attention: 4 warpgroups of 2 warps, 32 q-rows per warp --------
// Grid (16 q-tiles x 8 heads), block 256. wg w covers keys [w*256, w*256+256)
// (4 chunks of 64); warp wi covers rows wi*32..wi*32+31 (2 m-frags).
// B-fragments (K/V) loaded once per ks-step, reused for both m-frags ->
// halved crossbar bytes vs 16-row warps. 4-way split-KV merge at end.
#define BARW() asm volatile("bar.sync %0, 64;" :: "r"(wg + 1))

__global__ void __launch_bounds__(256, 1) attn_kernel(const float* __restrict__ Wr) {
    extern __shared__ __align__(16) char sm[];
    // Ksb: [4][2][64][36] = 73728 B @ 0
    // Vsb: [4][64][36]    = 36864 B @ 73728
    // Psb: [4][64][68]    = 69632 B @ 110592
    // coeff: [64]         = 256 B   @ 180224          (total 180480)
    float*    Ksb   = (float*)sm;
    float*    Vsb   = (float*)(sm + 73728);
    unsigned* Psb   = (unsigned*)(sm + 110592);
    float*    coeff = (float*)(sm + 180224);

    int h = blockIdx.y, q0 = blockIdx.x * 64;
    int tid = threadIdx.x, warp = tid >> 5, lane = tid & 31;
    int wg = warp >> 1, wi = warp & 1;
    int wtid = tid & 63;
    int g = lane >> 2, t = lane & 3;
    int hc = h * 32;
    const float scale = 0.0625f;

    float*    myK = Ksb + wg * 2 * 64 * 36;
    float*    myV = Vsb + wg * 64 * 36;
    unsigned* myP = Psb + wg * 64 * 68;
    unsigned* qbuf = Psb;                    // alias wg0 P, stride 36

    auto stageK = [&](int s, int k0) {
        float* dst = myK + s * 64 * 36;
        #pragma unroll
        for (int i = 0; i < 8; i++) {
            int f = wtid + i * 64;
            int r = f >> 3, c4 = f & 7;
            cp16(dst + r * 36 + c4 * 4, g_k + (k0 + r) * 256 + hc + c4 * 4);
        }
        CP_COMMIT();
    };
    auto stageV = [&](int k0) {
        #pragma unroll
        for (int i = 0; i < 8; i++) {
            int f = wtid + i * 64;
            int r = f >> 3, c4 = f & 7;
            cp16(myV + r * 36 + c4 * 4, g_v + (k0 + r) * 256 + hc + c4 * 4);
        }
        CP_COMMIT();
    };

    int kbase = wg * 256;
    stageK(0, kbase);           // overlap initial loads with q prologue
    stageV(kbase);

    // q tile into qbuf (tf32-pre-rounded by prep; fold in scale)
    #pragma unroll
    for (int i = 0; i < 2; i++) {
        int f = tid + i * 256;                 // 64 rows x 8 f4
        int r = f >> 3, c4 = f & 7;
        float4 a4 = *(const float4*)(g_q + (q0 + r) * 256 + hc + c4 * 4);
        qbuf[r*36 + c4*4+0] = __float_as_uint(a4.x * scale);
        qbuf[r*36 + c4*4+1] = __float_as_uint(a4.y * scale);
        qbuf[r*36 + c4*4+2] = __float_as_uint(a4.z * scale);
        qbuf[r*36 + c4*4+3] = __float_as_uint(a4.w * scale);
    }
    __syncthreads();

    if (tid < 64) {            // coeff[r] = sum_d q_scaled[r][d] * Wr[hc+d]
        float c = 0.f;
        #pragma unroll
        for (int d = 0; d < 32; d++)
            c = fmaf(__uint_as_float(qbuf[tid*36 + d]), Wr[hc + d], c);
        coeff[tid] = c;
    }
    __syncthreads();

    int rbase = wi * 32;
    unsigned qa[2][4][4];
    #pragma unroll
    for (int mf = 0; mf < 2; mf++) {
        int ra = rbase + mf * 16 + g, rb = ra + 8;
        #pragma unroll
        for (int ks = 0; ks < 4; ks++) {
            qa[mf][ks][0] = qbuf[ra*36 + ks*8 + t];
            qa[mf][ks][1] = qbuf[rb*36 + ks*8 + t];
            qa[mf][ks][2] = qbuf[ra*36 + ks*8 + t + 4];
            qa[mf][ks][3] = qbuf[rb*36 + ks*8 + t + 4];
        }
    }
    float cf[2][2];
    cf[0][0] = coeff[rbase + g];      cf[0][1] = coeff[rbase + 8 + g];
    cf[1][0] = coeff[rbase + 16 + g]; cf[1][1] = coeff[rbase + 24 + g];
    const float* relpa[2];
    const float* relpb[2];
    relpa[0] = g_rel + (q0 + rbase + g) * 1024;
    relpb[0] = g_rel + (q0 + rbase + 8 + g) * 1024;
    relpa[1] = g_rel + (q0 + rbase + 16 + g) * 1024;
    relpb[1] = g_rel + (q0 + rbase + 24 + g) * 1024;
    __syncthreads();          // qa/coeff consumed; P regions free for writing

    float mrun[2][2], lrun[2][2];
    float O[2][4][4];
    #pragma unroll
    for (int mf = 0; mf < 2; mf++) {
        mrun[mf][0] = -INFINITY; mrun[mf][1] = -INFINITY;
        lrun[mf][0] = 0.f;       lrun[mf][1] = 0.f;
        #pragma unroll
        for (int nf = 0; nf < 4; nf++)
            #pragma unroll
            for (int j = 0; j < 4; j++) O[mf][nf][j] = 0.f;
    }

    for (int ch = 0; ch < 4; ch++) {
        int s = ch & 1;
        int k0 = kbase + ch * 64;
        cp_wait<1>();                  // K(ch) done; [K(ch), V(ch)] pattern
        BARW();
        if (ch < 3) stageK(s ^ 1, k0 + 64);

        // S = q.k  (b-frags hoisted, reused across both m-frags)
        float S[2][8][4];
        #pragma unroll
        for (int mf = 0; mf < 2; mf++)
            #pragma unroll
            for (int nf = 0; nf < 8; nf++)
                #pragma unroll
                for (int j = 0; j < 4; j++) S[mf][nf][j] = 0.f;
        float* Kc = myK + s * 64 * 36;
        #pragma unroll
        for (int ks = 0; ks < 4; ks++) {
            unsigned b[8][2];
            #pragma unroll
            for (int nf = 0; nf < 8; nf++) {
                int nr = nf * 8 + g;
                b[nf][0] = __float_as_uint(Kc[nr*36 + ks*8 + t]);
                b[nf][1] = __float_as_uint(Kc[nr*36 + ks*8 + t + 4]);
            }
            #pragma unroll
            for (int mf = 0; mf < 2; mf++)
                #pragma unroll
                for (int nf = 0; nf < 8; nf++)
                    mma_tf32(S[mf][nf], qa[mf][ks], b[nf]);
        }

        // per m-frag: rel bias + online softmax + P store
        #pragma unroll
        for (int mf = 0; mf < 2; mf++) {
            int r0 = rbase + mf * 16 + g, r1 = r0 + 8;
            #pragma unroll
            for (int nf = 0; nf < 8; nf++) {
                float2 ra = *(const float2*)(relpa[mf] + k0 + nf*8 + 2*t);
                float2 rb = *(const float2*)(relpb[mf] + k0 + nf*8 + 2*t);
                S[mf][nf][0] += cf[mf][0] * ra.x;
                S[mf][nf][1] += cf[mf][0] * ra.y;
                S[mf][nf][2] += cf[mf][1] * rb.x;
                S[mf][nf][3] += cf[mf][1] * rb.y;
            }
            float mx0 = -INFINITY, mx1 = -INFINITY;
            #pragma unroll
            for (int nf = 0; nf < 8; nf++) {
                mx0 = fmaxf(mx0, fmaxf(S[mf][nf][0], S[mf][nf][1]));
                mx1 = fmaxf(mx1, fmaxf(S[mf][nf][2], S[mf][nf][3]));
            }
            mx0 = fmaxf(mx0, __shfl_xor_sync(0xffffffffu, mx0, 1));
            mx0 = fmaxf(mx0, __shfl_xor_sync(0xffffffffu, mx0, 2));
            mx1 = fmaxf(mx1, __shfl_xor_sync(0xffffffffu, mx1, 1));
            mx1 = fmaxf(mx1, __shfl_xor_sync(0xffffffffu, mx1, 2));
            float mn0 = fmaxf(mrun[mf][0], mx0), mn1 = fmaxf(mrun[mf][1], mx1);
            float corr0 = __expf(mrun[mf][0] - mn0);
            float corr1 = __expf(mrun[mf][1] - mn1);
            mrun[mf][0] = mn0; mrun[mf][1] = mn1;

            float ps0 = 0.f, ps1 = 0.f;
            #pragma unroll
            for (int nf = 0; nf < 8; nf++) {
                float p00 = __expf(S[mf][nf][0] - mn0);
                float p01 = __expf(S[mf][nf][1] - mn0);
                float p10 = __expf(S[mf][nf][2] - mn1);
                float p11 = __expf(S[mf][nf][3] - mn1);
                ps0 += p00 + p01; ps1 += p10 + p11;
                myP[r0*68 + nf*8 + 2*t]     = tf32r(p00);
                myP[r0*68 + nf*8 + 2*t + 1] = tf32r(p01);
                myP[r1*68 + nf*8 + 2*t]     = tf32r(p10);
                myP[r1*68 + nf*8 + 2*t + 1] = tf32r(p11);
            }
            ps0 += __shfl_xor_sync(0xffffffffu, ps0, 1);
            ps0 += __shfl_xor_sync(0xffffffffu, ps0, 2);
            ps1 += __shfl_xor_sync(0xffffffffu, ps1, 1);
            ps1 += __shfl_xor_sync(0xffffffffu, ps1, 2);
            lrun[mf][0] = lrun[mf][0] * corr0 + ps0;
            lrun[mf][1] = lrun[mf][1] * corr1 + ps1;
            #pragma unroll
            for (int nf = 0; nf < 4; nf++) {
                O[mf][nf][0] *= corr0; O[mf][nf][1] *= corr0;
                O[mf][nf][2] *= corr1; O[mf][nf][3] *= corr1;
            }
        }
        __syncwarp();   // order myP STS before LDS (rows warp-private)

        if (ch < 3) cp_wait<1>(); else cp_wait<0>();   // V(ch) done
        BARW();

        // O += P @ V  (v-frags hoisted, reused across both m-frags)
        #pragma unroll
        for (int ks = 0; ks < 8; ks++) {
            unsigned vb[4][2];
            #pragma unroll
            for (int nf = 0; nf < 4; nf++) {
                vb[nf][0] = __float_as_uint(myV[(ks*8 + t    )*36 + nf*8 + g]);
                vb[nf][1] = __float_as_uint(myV[(ks*8 + t + 4)*36 + nf*8 + g]);
            }
            #pragma unroll
            for (int mf = 0; mf < 2; mf++) {
                int r0 = rbase + mf * 16 + g, r1 = r0 + 8;
                unsigned pa[4];
                pa[0] = myP[r0*68 + ks*8 + t];
                pa[1] = myP[r1*68 + ks*8 + t];
                pa[2] = myP[r0*68 + ks*8 + t + 4];
                pa[3] = myP[r1*68 + ks*8 + t + 4];
                #pragma unroll
                for (int nf = 0; nf < 4; nf++)
                    mma_tf32(O[mf][nf], pa, vb[nf]);
            }
        }
        BARW();                        // wg done reading myV
        if (ch < 3) stageV(k0 + 64);
    }

    // ---- merge the 4 warpgroup partials ----
    __syncthreads();                   // everyone done; K region reusable
    float* buf = (float*)sm;           // [3][64][40]
    if (wg > 0) {
        float* o = buf + ((wg - 1) * 64 + wtid) * 40;
        #pragma unroll
        for (int mf = 0; mf < 2; mf++)
            #pragma unroll
            for (int nf = 0; nf < 4; nf++)
                #pragma unroll
                for (int j = 0; j < 4; j++)
                    o[mf*16 + nf*4 + j] = O[mf][nf][j];
        #pragma unroll
        for (int mf = 0; mf < 2; mf++)
            #pragma unroll
            for (int rr = 0; rr < 2; rr++) {
                o[32 + mf*4 + rr*2]     = mrun[mf][rr];
                o[32 + mf*4 + rr*2 + 1] = lrun[mf][rr];
            }
    }
    __syncthreads();
    if (wg == 0) {
        #pragma unroll
        for (int p = 0; p < 3; p++) {
            const float* o = buf + (p * 64 + wtid) * 40;
            #pragma unroll
            for (int mf = 0; mf < 2; mf++)
                #pragma unroll
                for (int rr = 0; rr < 2; rr++) {
                    float mB = o[32 + mf*4 + rr*2];
                    float lB = o[32 + mf*4 + rr*2 + 1];
                    float M  = fmaxf(mrun[mf][rr], mB);
                    float eA = __expf(mrun[mf][rr] - M);
                    float eB = __expf(mB - M);
                    lrun[mf][rr] = lrun[mf][rr] * eA + lB * eB;
                    mrun[mf][rr] = M;
                    #pragma unroll
                    for (int nf = 0; nf < 4; nf++) {
                        O[mf][nf][rr*2]   = O[mf][nf][rr*2]   * eA + o[mf*16 + nf*4 + rr*2]   * eB;
                        O[mf][nf][rr*2+1] = O[mf][nf][rr*2+1] * eA + o[mf*16 + nf*4 + rr*2+1] * eB;
                    }
                }
        }
        #pragma unroll
        for (int mf = 0; mf < 2; mf++) {
            float inv0 = 1.f / lrun[mf][0], inv1 = 1.f / lrun[mf][1];
            int r0 = rbase + mf * 16 + g, r1 = r0 + 8;
            #pragma unroll
            for (int nf = 0; nf < 4; nf++) {
                int col = hc + nf * 8 + 2 * t;
                *(float2*)(g_ctx + (q0 + r0) * 256 + col) =
                    make_float2(O[mf][nf][0] * inv0, O[mf][nf][1] * inv0);
                *(float2*)(g_ctx + (q0 + r1) * 256 + col) =
                    make_float2(O[mf][nf][2] * inv1, O[mf][nf][3] * inv1);
            }
        }
    }
}

// ---- launch --------------------------------------------------------------
extern "C" void kernel_launch(void* const* d_in, const int* in_sizes, int n_in,
                              void* d_out, int out_size) {
    const float* V   = (const float*)d_in[0];
    const float* K   = (const float*)d_in[1];
    const float* Q   = (const float*)d_in[2];
    const float* pos = (const float*)d_in[3];
    const float* Wq  = (const float*)d_in[4];
    const float* Wk  = (const float*)d_in[5];
    const float* Wv  = (const float*)d_in[6];
    const float* Wr  = (const float*)d_in[7];
    const float* Wo  = (const float*)d_in[8];
    const float* bo  = (const float*)d_in[9];
    float* out = (float*)d_out;

    cudaFuncSetAttribute(attn_kernel,
                         cudaFuncAttributeMaxDynamicSharedMemorySize, 180480);

    prep_kernel<<<dim3(32, 4, 4), 128>>>(Q, K, V, Wq, Wk, Wv, pos);
    attn_kernel<<<dim3(16, 8), 256, 180480>>>(Wr);
    out_kernel<<<dim3(32, 4), 128>>>(Wo, bo, out);
}